// round 8
// baseline (speedup 1.0000x reference)
#include <cuda_runtime.h>
#include <cuda_fp16.h>

// SpatialLoss: per-segment variance loss over batch 0 only.
// Round 8: lean issue path + plane-interleaved RED layout.
//  - g_sumh[oct][seg][4 half2]: a pixel's 8 red8s hit 8 different 32KB planes
//    (8 different L2 partitions; old layout serialized a segment on one LTS).
//  - segment base address computed once; per-oct offsets are immediates.
//  - straight-line unrolled body, minimal loop/addressing overhead.

#define NSEG    2048
#define PIX     (1024 * 1024)
#define TPB     256
#define NBLK    ((PIX / 4) / TPB)      // 1024
#define PLANE   (NSEG * 4)             // 8192 half2 per oct-plane (32KB)

__device__ __half2 g_sumh[8 * PLANE];  // [oct][seg][4 units]
__device__ float2  g_sc[NSEG];         // (ssq, count)
__device__ float2  g_acc;              // (loss, nz)

__device__ __forceinline__ void red8(__half2* p, __half2 a, __half2 b,
                                     __half2 c, __half2 d) {
    asm volatile("red.global.add.noftz.v4.f16x2 [%0], {%1,%2,%3,%4};"
                 :: "l"(p),
                    "r"(*(const unsigned*)&a), "r"(*(const unsigned*)&b),
                    "r"(*(const unsigned*)&c), "r"(*(const unsigned*)&d)
                 : "memory");
}
__device__ __forceinline__ void red2(float2* p, float a, float b) {
    asm volatile("red.global.add.v2.f32 [%0], {%1, %2};"
                 :: "l"(p), "f"(a), "f"(b) : "memory");
}

__global__ void zero_kernel() {
    const int i = blockIdx.x * blockDim.x + threadIdx.x;
    if (i < 8 * PLANE) ((unsigned*)g_sumh)[i] = 0u;
    const int j = i - 8 * PLANE;
    if (j >= 0 && j < NSEG) g_sc[j] = make_float2(0.0f, 0.0f);
    if (i == 0) g_acc = make_float2(0.0f, 0.0f);
}

template <int OCT>
__device__ __forceinline__ void do_oct(const float* __restrict__ f,
                                       __half2* r0, __half2* r1,
                                       __half2* r2, __half2* r3,
                                       __half2& q0, __half2& q1,
                                       __half2& q2, __half2& q3) {
    const float4 v0 = *(const float4*)(f + (size_t)(OCT * 8 + 0) * PIX);
    const float4 v1 = *(const float4*)(f + (size_t)(OCT * 8 + 1) * PIX);
    const float4 v2 = *(const float4*)(f + (size_t)(OCT * 8 + 2) * PIX);
    const float4 v3 = *(const float4*)(f + (size_t)(OCT * 8 + 3) * PIX);
    const float4 v4 = *(const float4*)(f + (size_t)(OCT * 8 + 4) * PIX);
    const float4 v5 = *(const float4*)(f + (size_t)(OCT * 8 + 5) * PIX);
    const float4 v6 = *(const float4*)(f + (size_t)(OCT * 8 + 6) * PIX);
    const float4 v7 = *(const float4*)(f + (size_t)(OCT * 8 + 7) * PIX);

    const __half2 a0 = __floats2half2_rn(v0.x, v1.x), b0 = __floats2half2_rn(v2.x, v3.x);
    const __half2 c0 = __floats2half2_rn(v4.x, v5.x), d0 = __floats2half2_rn(v6.x, v7.x);
    const __half2 a1 = __floats2half2_rn(v0.y, v1.y), b1 = __floats2half2_rn(v2.y, v3.y);
    const __half2 c1 = __floats2half2_rn(v4.y, v5.y), d1 = __floats2half2_rn(v6.y, v7.y);
    const __half2 a2 = __floats2half2_rn(v0.z, v1.z), b2 = __floats2half2_rn(v2.z, v3.z);
    const __half2 c2 = __floats2half2_rn(v4.z, v5.z), d2 = __floats2half2_rn(v6.z, v7.z);
    const __half2 a3 = __floats2half2_rn(v0.w, v1.w), b3 = __floats2half2_rn(v2.w, v3.w);
    const __half2 c3 = __floats2half2_rn(v4.w, v5.w), d3 = __floats2half2_rn(v6.w, v7.w);

    q0 = __hfma2(a0, a0, q0); q0 = __hfma2(b0, b0, q0);
    q0 = __hfma2(c0, c0, q0); q0 = __hfma2(d0, d0, q0);
    q1 = __hfma2(a1, a1, q1); q1 = __hfma2(b1, b1, q1);
    q1 = __hfma2(c1, c1, q1); q1 = __hfma2(d1, d1, q1);
    q2 = __hfma2(a2, a2, q2); q2 = __hfma2(b2, b2, q2);
    q2 = __hfma2(c2, c2, q2); q2 = __hfma2(d2, d2, q2);
    q3 = __hfma2(a3, a3, q3); q3 = __hfma2(b3, b3, q3);
    q3 = __hfma2(c3, c3, q3); q3 = __hfma2(d3, d3, q3);

    // per-oct plane offset is a compile-time immediate off the seg base
    red8(r0 + OCT * PLANE, a0, b0, c0, d0);
    red8(r1 + OCT * PLANE, a1, b1, c1, d1);
    red8(r2 + OCT * PLANE, a2, b2, c2, d2);
    red8(r3 + OCT * PLANE, a3, b3, c3, d3);
}

__global__ __launch_bounds__(TPB)
void accum_kernel(const int* __restrict__ sp, const float* __restrict__ feats) {
    const int t = blockIdx.x * TPB + threadIdx.x;
    const int p = t * 4;

    const int4 s4 = *(const int4*)(sp + p);
    __half2* r0 = g_sumh + s4.x * 4;   // one IMAD each; octs add immediates
    __half2* r1 = g_sumh + s4.y * 4;
    __half2* r2 = g_sumh + s4.z * 4;
    __half2* r3 = g_sumh + s4.w * 4;

    const float* f = feats + p;
    __half2 q0 = __float2half2_rn(0.0f), q1 = q0, q2 = q0, q3 = q0;

    do_oct<0>(f, r0, r1, r2, r3, q0, q1, q2, q3);
    do_oct<1>(f, r0, r1, r2, r3, q0, q1, q2, q3);
    do_oct<2>(f, r0, r1, r2, r3, q0, q1, q2, q3);
    do_oct<3>(f, r0, r1, r2, r3, q0, q1, q2, q3);
    do_oct<4>(f, r0, r1, r2, r3, q0, q1, q2, q3);
    do_oct<5>(f, r0, r1, r2, r3, q0, q1, q2, q3);
    do_oct<6>(f, r0, r1, r2, r3, q0, q1, q2, q3);
    do_oct<7>(f, r0, r1, r2, r3, q0, q1, q2, q3);

    red2(&g_sc[s4.x], __low2float(q0) + __high2float(q0), 1.0f);
    red2(&g_sc[s4.y], __low2float(q1) + __high2float(q1), 1.0f);
    red2(&g_sc[s4.z], __low2float(q2) + __high2float(q2), 1.0f);
    red2(&g_sc[s4.w], __low2float(q3) + __high2float(q3), 1.0f);
}

__global__ void reduce_kernel() {
    // one thread per segment; 8 blocks x 256 threads
    const int seg = blockIdx.x * 256 + threadIdx.x;
    float s2 = 0.0f;
    #pragma unroll
    for (int oct = 0; oct < 8; oct++) {
        const uint4 raw = *(const uint4*)(g_sumh + oct * PLANE + seg * 4);
        const float2 e0 = __half22float2(*(const __half2*)&raw.x);
        const float2 e1 = __half22float2(*(const __half2*)&raw.y);
        const float2 e2 = __half22float2(*(const __half2*)&raw.z);
        const float2 e3 = __half22float2(*(const __half2*)&raw.w);
        s2 += e0.x * e0.x + e0.y * e0.y + e1.x * e1.x + e1.y * e1.y
            + e2.x * e2.x + e2.y * e2.y + e3.x * e3.x + e3.y * e3.y;
    }
    const float2 sc = g_sc[seg];
    const float n  = sc.y;
    const float nn = fmaxf(n, 1.0f);
    const float per_seg = (sc.x - s2 / nn) / (64.0f * nn);
    float loss = (n >= 2.0f) ? per_seg : 0.0f;
    float nz   = (n > 0.0f) ? 1.0f : 0.0f;
    #pragma unroll
    for (int d = 16; d > 0; d >>= 1) {
        loss += __shfl_xor_sync(0xffffffffu, loss, d);
        nz   += __shfl_xor_sync(0xffffffffu, nz, d);
    }
    if ((threadIdx.x & 31) == 0) red2(&g_acc, loss, nz);
}

__global__ void finalize_kernel(float* __restrict__ out) {
    out[0] = g_acc.x / g_acc.y;
}

extern "C" void kernel_launch(void* const* d_in, const int* in_sizes, int n_in,
                              void* d_out, int out_size) {
    const int* sp;
    const float* feats;
    if (in_sizes[0] == 2 * 1024 * 1024) {
        sp    = (const int*)d_in[0];
        feats = (const float*)d_in[1];
    } else {
        sp    = (const int*)d_in[1];
        feats = (const float*)d_in[0];
    }

    const int zero_total = 8 * PLANE + NSEG;   // 67584
    zero_kernel<<<(zero_total + 255) / 256, 256>>>();

    accum_kernel<<<NBLK, TPB>>>(sp, feats);

    reduce_kernel<<<NSEG / 256, 256>>>();

    finalize_kernel<<<1, 1>>>((float*)d_out);
}

// round 9
// speedup vs baseline: 1.0155x; 1.0155x over previous
#include <cuda_runtime.h>
#include <cuda_fp16.h>

// SpatialLoss: per-segment variance loss over batch 0 only.
// Round 9: per-CTA counting sort. Pixel VALUES flow through the smem
// crossbar (STS.128 / LDS.128, 128B/cyc/SM) instead of atomic ALUs.
// Atomics remaining: 1 u32 hist-add + 1 scatter-add per px (cheap),
// one red.v4.f16x2 per (present segment, oct) flush, 1 ssq red1 per px.

#define NSEG   2048
#define PIX    (1024 * 1024)
#define TPB    512
#define NBLK   148
#define TOTG   (PIX / 4)            // 262144 groups of 4 px
#define MAXG   1772                 // ceil(TOTG / 148)
#define MAXPX  (MAXG * 4)           // 7088
#define GITER  4                    // ceil(MAXG / TPB)

// smem byte offsets
#define ST_STAGE 0                          // uint4[MAXPX]      113408
#define ST_POS   113408                     // u16 [MAXPX]        14176
#define ST_HIST  127584                     // u32 [NSEG]          8192
#define ST_BASE  135776                     // u32 [NSEG]          8192
#define ST_CURS  143968                     // u32 [NSEG]          8192
#define ST_WSUM  152160                     // u32 [32]
#define SMEM_BYTES 152320

__device__ __align__(16) __half2 g_sumh[NSEG * 32];  // [seg][32 half2] = 64 ch
__device__ float  g_ssq[NSEG];
__device__ float  g_cnt[NSEG];
__device__ float2 g_acc;

__device__ __forceinline__ void red8(__half2* p, __half2 a, __half2 b,
                                     __half2 c, __half2 d) {
    asm volatile("red.global.add.noftz.v4.f16x2 [%0], {%1,%2,%3,%4};"
                 :: "l"(p),
                    "r"(*(const unsigned*)&a), "r"(*(const unsigned*)&b),
                    "r"(*(const unsigned*)&c), "r"(*(const unsigned*)&d)
                 : "memory");
}
__device__ __forceinline__ void red1(float* p, float a) {
    asm volatile("red.global.add.f32 [%0], %1;" :: "l"(p), "f"(a) : "memory");
}
__device__ __forceinline__ void red2(float2* p, float a, float b) {
    asm volatile("red.global.add.v2.f32 [%0], {%1, %2};"
                 :: "l"(p), "f"(a), "f"(b) : "memory");
}

__global__ void zero_kernel() {
    const int i = blockIdx.x * blockDim.x + threadIdx.x;
    if (i < NSEG * 16) ((uint2*)g_sumh)[i] = make_uint2(0u, 0u);  // 32 half2/seg
    const int j = i - NSEG * 16;
    if (j >= 0 && j < NSEG) { g_ssq[j] = 0.0f; g_cnt[j] = 0.0f; }
    if (i == 0) g_acc = make_float2(0.0f, 0.0f);
}

__global__ __launch_bounds__(TPB, 1)
void accum_kernel(const int* __restrict__ sp, const float* __restrict__ feats) {
    extern __shared__ char smem[];
    uint4*          stage  = (uint4*)(smem + ST_STAGE);
    unsigned short* pos_of = (unsigned short*)(smem + ST_POS);
    unsigned*       hist   = (unsigned*)(smem + ST_HIST);
    unsigned*       sbase  = (unsigned*)(smem + ST_BASE);
    unsigned*       scurs  = (unsigned*)(smem + ST_CURS);
    unsigned*       wsum   = (unsigned*)(smem + ST_WSUM);

    const int tid  = threadIdx.x;
    const int lane = tid & 31;
    const int wid  = tid >> 5;

    const int gstart = (int)(((long long)blockIdx.x       * TOTG) / NBLK);
    const int gend   = (int)(((long long)(blockIdx.x + 1) * TOTG) / NBLK);
    const int4* sp4  = (const int4*)sp;

    // ---------- P0a: histogram of segment ids ----------
    for (int i = tid; i < NSEG; i += TPB) hist[i] = 0u;
    __syncthreads();
    #pragma unroll
    for (int k = 0; k < GITER; k++) {
        const int g = gstart + k * TPB + tid;
        if (g < gend) {
            const int4 s = sp4[g];
            atomicAdd(&hist[s.x], 1u); atomicAdd(&hist[s.y], 1u);
            atomicAdd(&hist[s.z], 1u); atomicAdd(&hist[s.w], 1u);
        }
    }
    __syncthreads();

    // ---------- P0b: exclusive prefix scan (2048 bins, 4/thread) ----------
    {
        const unsigned h0 = hist[4 * tid + 0], h1 = hist[4 * tid + 1];
        const unsigned h2 = hist[4 * tid + 2], h3 = hist[4 * tid + 3];
        const unsigned tsum = h0 + h1 + h2 + h3;
        unsigned incl = tsum;
        #pragma unroll
        for (int d = 1; d < 32; d <<= 1) {
            const unsigned n = __shfl_up_sync(0xffffffffu, incl, d);
            if (lane >= d) incl += n;
        }
        if (lane == 31) wsum[wid] = incl;
        __syncthreads();
        if (wid == 0) {
            unsigned v = (lane < 16) ? wsum[lane] : 0u;
            unsigned iv = v;
            #pragma unroll
            for (int d = 1; d < 16; d <<= 1) {
                const unsigned n = __shfl_up_sync(0xffffffffu, iv, d);
                if (lane >= d) iv += n;
            }
            if (lane < 16) wsum[lane] = iv;
        }
        __syncthreads();
        const unsigned wexcl = (wid == 0) ? 0u : wsum[wid - 1];
        unsigned run = wexcl + incl - tsum;
        sbase[4 * tid + 0] = run; scurs[4 * tid + 0] = run; run += h0;
        sbase[4 * tid + 1] = run; scurs[4 * tid + 1] = run; run += h1;
        sbase[4 * tid + 2] = run; scurs[4 * tid + 2] = run; run += h2;
        sbase[4 * tid + 3] = run; scurs[4 * tid + 3] = run;
    }
    __syncthreads();

    // ---------- P0c: scatter sorted positions ----------
    #pragma unroll
    for (int k = 0; k < GITER; k++) {
        const int g = gstart + k * TPB + tid;
        if (g < gend) {
            const int4 s = sp4[g];
            const int lp = (g - gstart) * 4;
            pos_of[lp + 0] = (unsigned short)atomicAdd(&scurs[s.x], 1u);
            pos_of[lp + 1] = (unsigned short)atomicAdd(&scurs[s.y], 1u);
            pos_of[lp + 2] = (unsigned short)atomicAdd(&scurs[s.z], 1u);
            pos_of[lp + 3] = (unsigned short)atomicAdd(&scurs[s.w], 1u);
        }
    }
    __syncthreads();

    // ---------- per-oct: stage sorted fp16, then per-segment sum ----------
    float q[GITER][4];
    #pragma unroll
    for (int k = 0; k < GITER; k++) { q[k][0] = q[k][1] = q[k][2] = q[k][3] = 0.f; }

    for (int oct = 0; oct < 8; oct++) {
        // P1: load 8 channels for this thread's pixel groups, stage sorted
        #pragma unroll
        for (int k = 0; k < GITER; k++) {
            const int g = gstart + k * TPB + tid;
            if (g < gend) {
                const int p = g * 4;
                const float* f = feats + (size_t)(oct * 8) * PIX + p;
                const float4 v0 = *(const float4*)(f + 0 * (size_t)PIX);
                const float4 v1 = *(const float4*)(f + 1 * (size_t)PIX);
                const float4 v2 = *(const float4*)(f + 2 * (size_t)PIX);
                const float4 v3 = *(const float4*)(f + 3 * (size_t)PIX);
                const float4 v4 = *(const float4*)(f + 4 * (size_t)PIX);
                const float4 v5 = *(const float4*)(f + 5 * (size_t)PIX);
                const float4 v6 = *(const float4*)(f + 6 * (size_t)PIX);
                const float4 v7 = *(const float4*)(f + 7 * (size_t)PIX);

                q[k][0] += v0.x*v0.x + v1.x*v1.x + v2.x*v2.x + v3.x*v3.x
                         + v4.x*v4.x + v5.x*v5.x + v6.x*v6.x + v7.x*v7.x;
                q[k][1] += v0.y*v0.y + v1.y*v1.y + v2.y*v2.y + v3.y*v3.y
                         + v4.y*v4.y + v5.y*v5.y + v6.y*v6.y + v7.y*v7.y;
                q[k][2] += v0.z*v0.z + v1.z*v1.z + v2.z*v2.z + v3.z*v3.z
                         + v4.z*v4.z + v5.z*v5.z + v6.z*v6.z + v7.z*v7.z;
                q[k][3] += v0.w*v0.w + v1.w*v1.w + v2.w*v2.w + v3.w*v3.w
                         + v4.w*v4.w + v5.w*v5.w + v6.w*v6.w + v7.w*v7.w;

                const ushort4 pos = ((const ushort4*)pos_of)[g - gstart];
                uint4 t;
                __half2 h;
                h = __floats2half2_rn(v0.x, v1.x); t.x = *(unsigned*)&h;
                h = __floats2half2_rn(v2.x, v3.x); t.y = *(unsigned*)&h;
                h = __floats2half2_rn(v4.x, v5.x); t.z = *(unsigned*)&h;
                h = __floats2half2_rn(v6.x, v7.x); t.w = *(unsigned*)&h;
                stage[pos.x] = t;
                h = __floats2half2_rn(v0.y, v1.y); t.x = *(unsigned*)&h;
                h = __floats2half2_rn(v2.y, v3.y); t.y = *(unsigned*)&h;
                h = __floats2half2_rn(v4.y, v5.y); t.z = *(unsigned*)&h;
                h = __floats2half2_rn(v6.y, v7.y); t.w = *(unsigned*)&h;
                stage[pos.y] = t;
                h = __floats2half2_rn(v0.z, v1.z); t.x = *(unsigned*)&h;
                h = __floats2half2_rn(v2.z, v3.z); t.y = *(unsigned*)&h;
                h = __floats2half2_rn(v4.z, v5.z); t.z = *(unsigned*)&h;
                h = __floats2half2_rn(v6.z, v7.z); t.w = *(unsigned*)&h;
                stage[pos.z] = t;
                h = __floats2half2_rn(v0.w, v1.w); t.x = *(unsigned*)&h;
                h = __floats2half2_rn(v2.w, v3.w); t.y = *(unsigned*)&h;
                h = __floats2half2_rn(v4.w, v5.w); t.z = *(unsigned*)&h;
                h = __floats2half2_rn(v6.w, v7.w); t.w = *(unsigned*)&h;
                stage[pos.w] = t;
            }
        }
        __syncthreads();

        // P2: per-segment register sums over contiguous sorted runs
        #pragma unroll
        for (int k = 0; k < 4; k++) {
            const int seg = tid + k * TPB;
            const unsigned cnt = hist[seg];
            if (cnt) {
                const unsigned b = sbase[seg];
                __half2 a0 = __float2half2_rn(0.f), a1 = a0, a2 = a0, a3 = a0;
                for (unsigned i = 0; i < cnt; i++) {
                    const uint4 r = stage[b + i];
                    a0 = __hadd2(a0, *(const __half2*)&r.x);
                    a1 = __hadd2(a1, *(const __half2*)&r.y);
                    a2 = __hadd2(a2, *(const __half2*)&r.z);
                    a3 = __hadd2(a3, *(const __half2*)&r.w);
                }
                red8(&g_sumh[seg * 32 + oct * 4], a0, a1, a2, a3);
            }
        }
        __syncthreads();
    }

    // ---------- P3: per-pixel ssq scatter (1 red1 per px) ----------
    #pragma unroll
    for (int k = 0; k < GITER; k++) {
        const int g = gstart + k * TPB + tid;
        if (g < gend) {
            const int4 s = sp4[g];
            red1(&g_ssq[s.x], q[k][0]);
            red1(&g_ssq[s.y], q[k][1]);
            red1(&g_ssq[s.z], q[k][2]);
            red1(&g_ssq[s.w], q[k][3]);
        }
    }

    // ---------- P4: flush counts from hist ----------
    #pragma unroll
    for (int k = 0; k < 4; k++) {
        const int seg = tid + k * TPB;
        const unsigned c = hist[seg];
        if (c) red1(&g_cnt[seg], (float)c);
    }
}

__global__ void reduce_kernel() {
    const int seg = blockIdx.x * 256 + threadIdx.x;
    float s2 = 0.0f;
    #pragma unroll
    for (int j = 0; j < 8; j++) {
        const uint4 raw = ((const uint4*)g_sumh)[seg * 8 + j];
        const float2 e0 = __half22float2(*(const __half2*)&raw.x);
        const float2 e1 = __half22float2(*(const __half2*)&raw.y);
        const float2 e2 = __half22float2(*(const __half2*)&raw.z);
        const float2 e3 = __half22float2(*(const __half2*)&raw.w);
        s2 += e0.x * e0.x + e0.y * e0.y + e1.x * e1.x + e1.y * e1.y
            + e2.x * e2.x + e2.y * e2.y + e3.x * e3.x + e3.y * e3.y;
    }
    const float n  = g_cnt[seg];
    const float nn = fmaxf(n, 1.0f);
    const float per_seg = (g_ssq[seg] - s2 / nn) / (64.0f * nn);
    float loss = (n >= 2.0f) ? per_seg : 0.0f;
    float nz   = (n > 0.0f) ? 1.0f : 0.0f;
    #pragma unroll
    for (int d = 16; d > 0; d >>= 1) {
        loss += __shfl_xor_sync(0xffffffffu, loss, d);
        nz   += __shfl_xor_sync(0xffffffffu, nz, d);
    }
    if ((threadIdx.x & 31) == 0) red2(&g_acc, loss, nz);
}

__global__ void finalize_kernel(float* __restrict__ out) {
    out[0] = g_acc.x / g_acc.y;
}

extern "C" void kernel_launch(void* const* d_in, const int* in_sizes, int n_in,
                              void* d_out, int out_size) {
    const int* sp;
    const float* feats;
    if (in_sizes[0] == 2 * 1024 * 1024) {
        sp    = (const int*)d_in[0];
        feats = (const float*)d_in[1];
    } else {
        sp    = (const int*)d_in[1];
        feats = (const float*)d_in[0];
    }

    cudaFuncSetAttribute(accum_kernel,
                         cudaFuncAttributeMaxDynamicSharedMemorySize, SMEM_BYTES);

    const int zero_total = NSEG * 16 + NSEG;
    zero_kernel<<<(zero_total + 255) / 256, 256>>>();

    accum_kernel<<<NBLK, TPB, SMEM_BYTES>>>(sp, feats);

    reduce_kernel<<<NSEG / 256, 256>>>();

    finalize_kernel<<<1, 1>>>((float*)d_out);
}